// round 17
// baseline (speedup 1.0000x reference)
#include <cuda_runtime.h>
#include <cuda_fp16.h>
#include <math.h>
#include <stdint.h>

#define L_SEQ   32768
#define HDIM    256
#define PDIM    128
#define NLAYERS 4
#define NCHUNK  256
#define TCHUNK  128

// ---------------- scratch (static __device__, no allocation) ----------------
__device__ float  g_x  [L_SEQ*HDIM];
__device__ float  g_bu [L_SEQ*HDIM];
__device__ __half g_h  [L_SEQ*HDIM];   // LN output (fp16)
__device__ __half g_xs [L_SEQ*HDIM];   // scan output (fp16, descaled)
__device__ __half g_xh [L_SEQ*HDIM];   // rounded x for head
// transposed fp16 weights: [N][K] layout, K contiguous
__device__ __half g_Wbt[NLAYERS][HDIM*HDIM];   // row-scaled by s_p
__device__ __half g_Wct[NLAYERS][HDIM*HDIM];
__device__ __half g_W1t[NLAYERS][HDIM*HDIM];
__device__ __half g_W2t[NLAYERS][HDIM*HDIM];
__device__ __half g_Wot[128*HDIM];     // W_out^T zero-padded to 128 rows
__device__ float2 g_lam [NLAYERS][PDIM];
__device__ float2 g_lamT[NLAYERS][PDIM];
__device__ float  g_sinv[NLAYERS][PDIM];   // 1/s_p (power of two)
__device__ float2 g_E [NCHUNK*PDIM];
__device__ float  g_x0[HDIM];

// ---------------- PTX helpers ----------------
__device__ __forceinline__ uint32_t smem_u32(const void* p) {
    uint32_t a;
    asm("{ .reg .u64 t; cvta.to.shared.u64 t, %1; cvt.u32.u64 %0, t; }" : "=r"(a) : "l"(p));
    return a;
}
__device__ __forceinline__ void ldm4(uint32_t* r, uint32_t addr) {
    asm volatile("ldmatrix.sync.aligned.m8n8.x4.shared.b16 {%0,%1,%2,%3}, [%4];"
                 : "=r"(r[0]), "=r"(r[1]), "=r"(r[2]), "=r"(r[3]) : "r"(addr));
}
__device__ __forceinline__ void mma_f16(float* c, const uint32_t* a, const uint32_t* b) {
    asm volatile("mma.sync.aligned.m16n8k16.row.col.f32.f16.f16.f32 "
                 "{%0,%1,%2,%3}, {%4,%5,%6,%7}, {%8,%9}, {%0,%1,%2,%3};"
                 : "+f"(c[0]), "+f"(c[1]), "+f"(c[2]), "+f"(c[3])
                 : "r"(a[0]), "r"(a[1]), "r"(a[2]), "r"(a[3]), "r"(b[0]), "r"(b[1]));
}
__device__ __forceinline__ void cp16(uint32_t saddr, const void* gaddr) {
    asm volatile("cp.async.cg.shared.global [%0], [%1], 16;" :: "r"(saddr), "l"(gaddr));
}
#define CP_COMMIT() asm volatile("cp.async.commit_group;" ::: "memory")
#define CP_WAIT1()  asm volatile("cp.async.wait_group 1;" ::: "memory")
#define CP_WAIT0()  asm volatile("cp.async.wait_group 0;" ::: "memory")

__device__ __forceinline__ float gelu_f(float n) {
    float t = 0.7978845608028654f * (n + 0.044715f * n*n*n);
    return 0.5f * n * (1.f + tanhf(t));
}

// ---------------- setup kernels ----------------
__global__ void expand_kernel(const float* __restrict__ latent,
                              const float* __restrict__ W,
                              const float* __restrict__ b)
{
    int h = threadIdx.x;
    float s = 0.f;
    for (int l = 0; l < HDIM; l++) s += latent[l] * W[l*HDIM + h];
    s += b[h];
    g_x0[h] = s > 0.f ? s : 0.01f * s;
}

__global__ void broadcast_kernel()
{
    size_t n = (size_t)L_SEQ * HDIM / 4;
    const float4* src = (const float4*)g_x0;
    float4* dst = (float4*)g_x;
    for (size_t i = (size_t)blockIdx.x*blockDim.x + threadIdx.x; i < n;
         i += (size_t)gridDim.x*blockDim.x)
        dst[i] = src[i & (HDIM/4 - 1)];
}

__global__ void setup_params(const float* __restrict__ Lre, const float* __restrict__ Lim,
                             const float* __restrict__ Bre, const float* __restrict__ Bim,
                             const float* __restrict__ Cre, const float* __restrict__ Cim,
                             const float* __restrict__ log_step)
{
    int layer = blockIdx.x;
    int p = threadIdx.x;                 // 128 threads
    float step = expf(log_step[layer*PDIM + p]);
    float lr = Lre[layer*PDIM + p], li = Lim[layer*PDIM + p];
    float er  = expf(lr*step);
    float lbr = er * cosf(li*step);
    float lbi = er * sinf(li*step);
    g_lam[layer][p] = make_float2(lbr, lbi);
    float tr = lbr, ti = lbi;
    #pragma unroll
    for (int i = 0; i < 7; i++) { float nr2 = tr*tr - ti*ti; ti = 2.f*tr*ti; tr = nr2; }
    g_lamT[layer][p] = make_float2(tr, ti);
    float nr = lbr - 1.f, ni = lbi;
    float den = lr*lr + li*li;
    float fr = (nr*lr + ni*li) / den;
    float fi = (ni*lr - nr*li) / den;
    float fmag = sqrtf(fr*fr + fi*fi);
    float s = exp2f(rintf(-log2f(fmag)));   // exact power of two ~ 1/|f|
    g_sinv[layer][p] = 1.f / s;
    float frs = fr * s, fis = fi * s;
    const float* brp = Bre + ((size_t)layer*PDIM + p)*HDIM;
    const float* bip = Bim + ((size_t)layer*PDIM + p)*HDIM;
    for (int h = 0; h < HDIM; h++) {
        float br = brp[h], bi = bip[h];
        g_Wbt[layer][p*HDIM + h]        = __float2half_rn(frs*br - fis*bi);
        g_Wbt[layer][(PDIM+p)*HDIM + h] = __float2half_rn(frs*bi + fis*br);
        g_Wct[layer][h*HDIM + p]        = __float2half_rn( 2.f * Cre[((size_t)layer*HDIM + h)*PDIM + p]);
        g_Wct[layer][h*HDIM + PDIM + p] = __float2half_rn(-2.f * Cim[((size_t)layer*HDIM + h)*PDIM + p]);
    }
}

// one kernel converting W1, W2 (all layers) and W_out (transpose + fp16)
__global__ void convert_all(const float* __restrict__ W1, const float* __restrict__ W2,
                            const float* __restrict__ Wout)
{
    const int total1 = NLAYERS*HDIM*HDIM;
    const int total  = 2*total1 + 128*HDIM;
    for (int idx = blockIdx.x*blockDim.x + threadIdx.x; idx < total;
         idx += gridDim.x*blockDim.x) {
        if (idx < total1) {
            int l = idx / (HDIM*HDIM), r = idx - l*(HDIM*HDIM);
            int n = r / HDIM, k = r - n*HDIM;
            g_W1t[l][r] = __float2half_rn(W1[(size_t)l*HDIM*HDIM + k*HDIM + n]);
        } else if (idx < 2*total1) {
            int j = idx - total1;
            int l = j / (HDIM*HDIM), r = j - l*(HDIM*HDIM);
            int n = r / HDIM, k = r - n*HDIM;
            g_W2t[l][r] = __float2half_rn(W2[(size_t)l*HDIM*HDIM + k*HDIM + n]);
        } else {
            int j = idx - 2*total1;
            int n = j >> 8, k = j & 255;
            g_Wot[j] = (n < 64) ? __float2half_rn(Wout[k*64 + n]) : __float2half_rn(0.f);
        }
    }
}

// ---------------- LayerNorm (warp per row, float4 loads) -> fp16 (prenorm only) ----------------
__global__ void ln_act_kernel(const float* __restrict__ X, __half* __restrict__ Y,
                              const float* __restrict__ scale, const float* __restrict__ bias)
{
    int row  = blockIdx.x * (blockDim.x >> 5) + (threadIdx.x >> 5);
    int lane = threadIdx.x & 31;
    int c0 = lane * 8;
    const float* x = X + (size_t)row * HDIM;
    float4 a = *(const float4*)(x + c0);
    float4 b = *(const float4*)(x + c0 + 4);
    float v[8] = {a.x, a.y, a.z, a.w, b.x, b.y, b.z, b.w};
    float s = 0.f, s2 = 0.f;
    #pragma unroll
    for (int i = 0; i < 8; i++) { s += v[i]; s2 += v[i]*v[i]; }
    #pragma unroll
    for (int o = 16; o; o >>= 1) {
        s  += __shfl_xor_sync(0xffffffffu, s,  o);
        s2 += __shfl_xor_sync(0xffffffffu, s2, o);
    }
    float mu  = s  * (1.f/HDIM);
    float var = s2 * (1.f/HDIM) - mu*mu;
    float rs  = rsqrtf(var + 1e-6f);
    float4 sc0 = *(const float4*)(scale + c0);
    float4 sc1 = *(const float4*)(scale + c0 + 4);
    float4 bi0 = *(const float4*)(bias + c0);
    float4 bi1 = *(const float4*)(bias + c0 + 4);
    float scv[8] = {sc0.x, sc0.y, sc0.z, sc0.w, sc1.x, sc1.y, sc1.z, sc1.w};
    float biv[8] = {bi0.x, bi0.y, bi0.z, bi0.w, bi1.x, bi1.y, bi1.z, bi1.w};
    __half out[8];
    #pragma unroll
    for (int i = 0; i < 8; i++)
        out[i] = __float2half_rn((v[i] - mu) * rs * scv[i] + biv[i]);
    *(uint4*)(Y + (size_t)row*HDIM + c0) = *(uint4*)out;
}

// scanC with inline chunk-prefix; output descaled by 1/s_p then fp16-rounded
__global__ void scanC_kernel(const float* __restrict__ Bu, __half* __restrict__ XS, int layer)
{
    int c = blockIdx.x, p = threadIdx.x;
    float2 lamT = g_lamT[layer][p];
    float2 lam  = g_lam[layer][p];
    float inv   = g_sinv[layer][p];
    float xr = 0.f, xi = 0.f;
    for (int j = 0; j < c; j++) {
        float2 e = g_E[j*PDIM + p];
        float nr = lamT.x*xr - lamT.y*xi + e.x;
        float ni = lamT.x*xi + lamT.y*xr + e.y;
        xr = nr; xi = ni;
    }
    const float* b = Bu + (size_t)c * TCHUNK * HDIM;
    __half* o = XS + (size_t)c * TCHUNK * HDIM;
    for (int t = 0; t < TCHUNK; t++) {
        float br = b[t*HDIM + p], bi = b[t*HDIM + PDIM + p];
        float nr = lam.x*xr - lam.y*xi + br;
        float ni = lam.x*xi + lam.y*xr + bi;
        xr = nr; xi = ni;
        o[t*HDIM + p]        = __float2half_rn(xr * inv);
        o[t*HDIM + PDIM + p] = __float2half_rn(xi * inv);
    }
}

// ---------------- fp16 mma GEMM common ----------------
#define SPAD 40                       // smem row stride in halves (80B, 16B-aligned)
#define BUFSZ (128*SPAD*2)            // 10240 B per 128-row operand buffer
#define SMEM_G4 (4*BUFSZ)             // plain: [A,B] x 2 bufs
#define SMEM_G6 (6*BUFSZ)             // GLU:  [A,B1,B2] x 2 bufs
#define DLN_ABUF  BUFSZ               // 10240 (A: 128 rows)
#define DLN_BBUF  (256*SPAD*2)        // 20480 (B: 256 rows)
#define DLN_STAGE (DLN_ABUF + DLN_BBUF)
#define SMEM_DLN  (2*DLN_STAGE)       // 61440
#define BUS_STRIDE 260                // fp32 words per row in Bu smem dump
#define SMEM_BUS  (128*BUS_STRIDE*4)  // 133120 (aliases staging)

struct LaneAddr { int a_off, b_off; };
__device__ __forceinline__ LaneAddr lane_addr(int lane, int wm, int wn) {
    LaneAddr la;
    int a_r = lane & 15, a_c = (lane >> 4) * 8;
    int b_q = lane >> 3, b_r = lane & 7;
    int b_n_add = (b_q >> 1) * 8 + b_r;
    int b_k_add = (b_q & 1) * 8;
    la.a_off = (wm + a_r)*SPAD + a_c;
    la.b_off = (wn + b_n_add)*SPAD + b_k_add;
    return la;
}

// C[m0:+128, n0:+128] = A[m0:,K=256] * B^T[n0:,K=256]  (B stored [N][K])
// 256 threads, 8 warps (2M x 4N), warp tile 64x32, 2 CTAs/SM
__global__ __launch_bounds__(256, 2) void mma_gemm(
    const __half* __restrict__ A, const __half* __restrict__ B,
    float* __restrict__ C, int ldc, int nvalid,
    const float* __restrict__ bias)
{
    extern __shared__ __align__(16) char smem[];
    uint32_t sb = smem_u32(smem);
    int tid = threadIdx.x;
    int wid = tid >> 5, lane = tid & 31;
    int m0 = blockIdx.y * 128;
    int n0 = blockIdx.x * 128;
    int wm = (wid >> 2) * 64;
    int wn = (wid & 3) * 32;

    float acc[4][4][4];
    #pragma unroll
    for (int i = 0; i < 4; i++)
        #pragma unroll
        for (int j = 0; j < 4; j++)
            #pragma unroll
            for (int q = 0; q < 4; q++) acc[i][j][q] = 0.f;

    #define STAGE(k0, buf) do { \
        uint32_t ab = sb + (buf)*2*BUFSZ; \
        uint32_t bb = ab + BUFSZ; \
        _Pragma("unroll") \
        for (int i = 0; i < 2; i++) { \
            int idx = tid + i*256; \
            int r = idx >> 2, cg = (idx & 3) * 8; \
            uint32_t so = (uint32_t)((r*SPAD + cg) * 2); \
            cp16(ab + so, A + (size_t)(m0 + r)*HDIM + (k0) + cg); \
            cp16(bb + so, B + (size_t)(n0 + r)*HDIM + (k0) + cg); \
        } \
        CP_COMMIT(); } while (0)

    LaneAddr la = lane_addr(lane, wm, wn);

    STAGE(0, 0);
    for (int kc = 0; kc < 8; kc++) {
        if (kc < 7) STAGE((kc+1)*32, (kc+1) & 1);
        if (kc < 7) CP_WAIT1(); else CP_WAIT0();
        __syncthreads();
        uint32_t bbuf = sb + (kc & 1)*2*BUFSZ;
        uint32_t aA = bbuf, aB = bbuf + BUFSZ;
        #pragma unroll
        for (int ks = 0; ks < 2; ks++) {
            uint32_t bh[2][4];
            #pragma unroll
            for (int nf2 = 0; nf2 < 2; nf2++) {
                uint32_t boff = (uint32_t)((la.b_off + nf2*16*SPAD + ks*16) * 2);
                ldm4(bh[nf2], aB + boff);
            }
            uint32_t ah[4][4];
            #pragma unroll
            for (int mf = 0; mf < 4; mf++) {
                uint32_t aoff = (uint32_t)((la.a_off + mf*16*SPAD + ks*16) * 2);
                ldm4(ah[mf], aA + aoff);
            }
            #pragma unroll
            for (int mf = 0; mf < 4; mf++)
                #pragma unroll
                for (int nf = 0; nf < 4; nf++)
                    mma_f16(acc[mf][nf], ah[mf], &bh[nf >> 1][(nf & 1)*2]);
        }
        __syncthreads();
    }
    #undef STAGE

    int tr = lane >> 2, tc = (lane & 3) * 2;
    #pragma unroll
    for (int mf = 0; mf < 4; mf++) {
        #pragma unroll
        for (int nf = 0; nf < 4; nf++) {
            int col = n0 + wn + nf*8 + tc;
            if (col < nvalid) {
                #pragma unroll
                for (int hrow = 0; hrow < 2; hrow++) {
                    int m = m0 + wm + mf*16 + tr + hrow*8;
                    float v0 = acc[mf][nf][hrow*2+0];
                    float v1 = acc[mf][nf][hrow*2+1];
                    if (bias) { v0 += bias[col]; v1 += bias[col+1]; }
                    *(float2*)(C + (size_t)m*ldc + col) = make_float2(v0, v1);
                }
            }
        }
    }
}

// ---- fused Bu GEMM + within-chunk scan: Bu = h @ Wbt^T (128x256 tile = one chunk),
//      writes Bu to gmem AND computes E_c = chunk-end state, all in one kernel ----
__global__ __launch_bounds__(256) void gemm_bu_scan(
    const __half* __restrict__ A,      // h
    const __half* __restrict__ B,      // Wbt [256][256]
    float* __restrict__ Bu, int layer)
{
    extern __shared__ __align__(16) char smem[];
    uint32_t sb = smem_u32(smem);
    float* sbu = (float*)smem;         // [128][BUS_STRIDE] after mainloop
    int tid = threadIdx.x;
    int wid = tid >> 5, lane = tid & 31;
    int m0 = blockIdx.x * 128;         // == chunk * TCHUNK
    int wm = (wid >> 2) * 64;
    int wn = (wid & 3) * 64;

    float acc[4][8][4];
    #pragma unroll
    for (int i = 0; i < 4; i++)
        #pragma unroll
        for (int j = 0; j < 8; j++)
            #pragma unroll
            for (int q = 0; q < 4; q++) acc[i][j][q] = 0.f;

    #define STAGED(k0, buf) do { \
        uint32_t ab = sb + (buf)*DLN_STAGE; \
        uint32_t bb = ab + DLN_ABUF; \
        _Pragma("unroll") \
        for (int i = 0; i < 6; i++) { \
            int idx = tid + i*256; \
            if (idx < 512) { \
                int r = idx >> 2, cg = (idx & 3) * 8; \
                cp16(ab + (uint32_t)((r*SPAD + cg)*2), A + (size_t)(m0 + r)*HDIM + (k0) + cg); \
            } else { \
                int j = idx - 512; \
                int r = j >> 2, cg = (j & 3) * 8; \
                cp16(bb + (uint32_t)((r*SPAD + cg)*2), B + (size_t)r*HDIM + (k0) + cg); \
            } \
        } \
        CP_COMMIT(); } while (0)

    LaneAddr la = lane_addr(lane, wm, wn);

    STAGED(0, 0);
    for (int kc = 0; kc < 8; kc++) {
        if (kc < 7) STAGED((kc+1)*32, (kc+1) & 1);
        if (kc < 7) CP_WAIT1(); else CP_WAIT0();
        __syncthreads();
        uint32_t ab = sb + (kc & 1)*DLN_STAGE;
        uint32_t bbuf = ab + DLN_ABUF;
        #pragma unroll
        for (int ks = 0; ks < 2; ks++) {
            uint32_t bh[4][4];
            #pragma unroll
            for (int nf2 = 0; nf2 < 4; nf2++) {
                uint32_t boff = (uint32_t)((la.b_off + nf2*16*SPAD + ks*16) * 2);
                ldm4(bh[nf2], bbuf + boff);
            }
            uint32_t ah[4][4];
            #pragma unroll
            for (int mf = 0; mf < 4; mf++) {
                uint32_t aoff = (uint32_t)((la.a_off + mf*16*SPAD + ks*16) * 2);
                ldm4(ah[mf], ab + aoff);
            }
            #pragma unroll
            for (int mf = 0; mf < 4; mf++)
                #pragma unroll
                for (int nf = 0; nf < 8; nf++)
                    mma_f16(acc[mf][nf], ah[mf], &bh[nf >> 1][(nf & 1)*2]);
        }
        __syncthreads();
    }
    #undef STAGED

    // dump accumulators (the whole Bu chunk) to smem
    int tr = lane >> 2, tc = (lane & 3) * 2;
    #pragma unroll
    for (int mf = 0; mf < 4; mf++)
        #pragma unroll
        for (int hrow = 0; hrow < 2; hrow++) {
            int ml = wm + mf*16 + tr + hrow*8;
            #pragma unroll
            for (int nf = 0; nf < 8; nf++) {
                int col = wn + nf*8 + tc;
                *(float2*)(sbu + ml*BUS_STRIDE + col) =
                    make_float2(acc[mf][nf][hrow*2+0], acc[mf][nf][hrow*2+1]);
            }
        }
    __syncthreads();

    if (tid < 128) {
        // within-chunk scan over t for channel pair p = tid
        int p = tid;
        float2 lam = g_lam[layer][p];
        float xr = 0.f, xi = 0.f;
        for (int t = 0; t < TCHUNK; t++) {
            float br = sbu[t*BUS_STRIDE + p];
            float bi = sbu[t*BUS_STRIDE + PDIM + p];
            float nr = lam.x*xr - lam.y*xi + br;
            float ni = lam.x*xi + lam.y*xr + bi;
            xr = nr; xi = ni;
        }
        g_E[blockIdx.x*PDIM + p] = make_float2(xr, xi);
    } else {
        // stream Bu chunk to gmem (float4)
        int j = tid - 128;              // 0..127
        #pragma unroll
        for (int it = 0; it < 64; it++) {
            int idx = it*128 + j;       // 0..8191 float4s
            int row = idx >> 6, c4 = (idx & 63) * 4;
            *(float4*)(Bu + (size_t)(m0 + row)*HDIM + c4) =
                *(const float4*)(sbu + row*BUS_STRIDE + c4);
        }
    }
}

// ---- fused t1 GEMM + h*D + LayerNorm + gelu -> h (fp16). CTA tile 128x256, no t1 write ----
__global__ __launch_bounds__(256) void gemm_d_ln(
    const __half* __restrict__ A,      // xs
    const __half* __restrict__ B,      // Wct [256][256]
    const __half* __restrict__ U,      // h (for D term)
    const float* __restrict__ Dv,
    const float* __restrict__ scale, const float* __restrict__ bias,
    __half* __restrict__ Y)            // h out
{
    extern __shared__ __align__(16) char smem[];
    uint32_t sb = smem_u32(smem);
    int tid = threadIdx.x;
    int wid = tid >> 5, lane = tid & 31;
    int m0 = blockIdx.x * 128;
    int wm = (wid >> 2) * 64;    // 0 or 64
    int wn = (wid & 3) * 64;     // 0,64,128,192

    float acc[4][8][4];
    #pragma unroll
    for (int i = 0; i < 4; i++)
        #pragma unroll
        for (int j = 0; j < 8; j++)
            #pragma unroll
            for (int q = 0; q < 4; q++) acc[i][j][q] = 0.f;

    #define STAGED(k0, buf) do { \
        uint32_t ab = sb + (buf)*DLN_STAGE; \
        uint32_t bb = ab + DLN_ABUF; \
        _Pragma("unroll") \
        for (int i = 0; i < 6; i++) { \
            int idx = tid + i*256; \
            if (idx < 512) { \
                int r = idx >> 2, cg = (idx & 3) * 8; \
                cp16(ab + (uint32_t)((r*SPAD + cg)*2), A + (size_t)(m0 + r)*HDIM + (k0) + cg); \
            } else { \
                int j = idx - 512; \
                int r = j >> 2, cg = (j & 3) * 8; \
                cp16(bb + (uint32_t)((r*SPAD + cg)*2), B + (size_t)r*HDIM + (k0) + cg); \
            } \
        } \
        CP_COMMIT(); } while (0)

    LaneAddr la = lane_addr(lane, wm, wn);

    STAGED(0, 0);
    for (int kc = 0; kc < 8; kc++) {
        if (kc < 7) STAGED((kc+1)*32, (kc+1) & 1);
        if (kc < 7) CP_WAIT1(); else CP_WAIT0();
        __syncthreads();
        uint32_t ab = sb + (kc & 1)*DLN_STAGE;
        uint32_t bbuf = ab + DLN_ABUF;
        #pragma unroll
        for (int ks = 0; ks < 2; ks++) {
            uint32_t bh[4][4];
            #pragma unroll
            for (int nf2 = 0; nf2 < 4; nf2++) {
                uint32_t boff = (uint32_t)((la.b_off + nf2*16*SPAD + ks*16) * 2);
                ldm4(bh[nf2], bbuf + boff);
            }
            uint32_t ah[4][4];
            #pragma unroll
            for (int mf = 0; mf < 4; mf++) {
                uint32_t aoff = (uint32_t)((la.a_off + mf*16*SPAD + ks*16) * 2);
                ldm4(ah[mf], ab + aoff);
            }
            #pragma unroll
            for (int mf = 0; mf < 4; mf++)
                #pragma unroll
                for (int nf = 0; nf < 8; nf++)
                    mma_f16(acc[mf][nf], ah[mf], &bh[nf >> 1][(nf & 1)*2]);
        }
        __syncthreads();
    }
    #undef STAGED

    // ---- epilogue: v = acc + U*Dv ; row LN stats ; gelu ; fp16 store ----
    int tr = lane >> 2, tc = (lane & 3) * 2;
    float psum[8], psq[8];
    #pragma unroll
    for (int r = 0; r < 8; r++) { psum[r] = 0.f; psq[r] = 0.f; }

    #pragma unroll
    for (int mf = 0; mf < 4; mf++) {
        #pragma unroll
        for (int hrow = 0; hrow < 2; hrow++) {
            int ml = wm + mf*16 + tr + hrow*8;
            int ridx = mf*2 + hrow;
            #pragma unroll
            for (int nf = 0; nf < 8; nf++) {
                int col = wn + nf*8 + tc;
                size_t ub = (size_t)(m0 + ml)*HDIM + col;
                float v0 = acc[mf][nf][hrow*2+0] + __half2float(U[ub])   * Dv[col];
                float v1 = acc[mf][nf][hrow*2+1] + __half2float(U[ub+1]) * Dv[col+1];
                acc[mf][nf][hrow*2+0] = v0;
                acc[mf][nf][hrow*2+1] = v1;
                psum[ridx] += v0 + v1;
                psq[ridx]  += v0*v0 + v1*v1;
            }
        }
    }
    // reduce across 4 lanes sharing a row (lane bits 0-1)
    #pragma unroll
    for (int r = 0; r < 8; r++) {
        psum[r] += __shfl_xor_sync(0xffffffffu, psum[r], 1);
        psq[r]  += __shfl_xor_sync(0xffffffffu, psq[r],  1);
        psum[r] += __shfl_xor_sync(0xffffffffu, psum[r], 2);
        psq[r]  += __shfl_xor_sync(0xffffffffu, psq[r],  2);
    }
    float* red_sum = (float*)smem;           // [128][4]
    float* red_sq  = (float*)smem + 512;     // [128][4]
    float2* stats  = (float2*)((float*)smem + 1024);  // [128]
    int wn_idx = wid & 3;
    if ((lane & 3) == 0) {
        #pragma unroll
        for (int mf = 0; mf < 4; mf++)
            #pragma unroll
            for (int hrow = 0; hrow < 2; hrow++) {
                int ml = wm + mf*16 + tr + hrow*8;
                int ridx = mf*2 + hrow;
                red_sum[ml*4 + wn_idx] = psum[ridx];
                red_sq [ml*4 + wn_idx] = psq[ridx];
            }
    }
    __syncthreads();
    if (tid < 128) {
        float s = red_sum[tid*4] + red_sum[tid*4+1] + red_sum[tid*4+2] + red_sum[tid*4+3];
        float q = red_sq [tid*4] + red_sq [tid*4+1] + red_sq [tid*4+2] + red_sq [tid*4+3];
        float mu  = s * (1.f/HDIM);
        float var = q * (1.f/HDIM) - mu*mu;
        stats[tid] = make_float2(mu, rsqrtf(var + 1e-6f));
    }
    __syncthreads();
    #pragma unroll
    for (int mf = 0; mf < 4; mf++) {
        #pragma unroll
        for (int hrow = 0; hrow < 2; hrow++) {
            int ml = wm + mf*16 + tr + hrow*8;
            float2 st = stats[ml];
            #pragma unroll
            for (int nf = 0; nf < 8; nf++) {
                int col = wn + nf*8 + tc;
                float n0 = (acc[mf][nf][hrow*2+0] - st.x) * st.y * scale[col]   + bias[col];
                float n1 = (acc[mf][nf][hrow*2+1] - st.x) * st.y * scale[col+1] + bias[col+1];
                __half2 hv = __halves2half2(__float2half_rn(gelu_f(n0)),
                                            __float2half_rn(gelu_f(n1)));
                *(__half2*)(Y + (size_t)(m0 + ml)*HDIM + col) = hv;
            }
        }
    }
}

// ---- fused GLU GEMM pair: x += (A@W1^T+b1) * sigmoid(A@W2^T+b2); optional fp16 copy ----
__global__ __launch_bounds__(256) void mma_gemm_glu(
    const __half* __restrict__ A,
    const __half* __restrict__ B1, const __half* __restrict__ B2,
    const float* __restrict__ b1, const float* __restrict__ b2,
    float* __restrict__ X, __half* __restrict__ Xr, int emit_round)
{
    extern __shared__ __align__(16) char smem[];
    uint32_t sb = smem_u32(smem);
    int tid = threadIdx.x;
    int wid = tid >> 5, lane = tid & 31;
    int m0 = blockIdx.y * 128;
    int n0 = blockIdx.x * 128;
    int wm = (wid >> 2) * 64;
    int wn = (wid & 3) * 32;

    float acc1[4][4][4], acc2[4][4][4];
    #pragma unroll
    for (int i = 0; i < 4; i++)
        #pragma unroll
        for (int j = 0; j < 4; j++)
            #pragma unroll
            for (int q = 0; q < 4; q++) { acc1[i][j][q] = 0.f; acc2[i][j][q] = 0.f; }

    #define STAGE6(k0, buf) do { \
        uint32_t ab  = sb + (buf)*3*BUFSZ; \
        uint32_t bb1 = ab + BUFSZ; \
        uint32_t bb2 = ab + 2*BUFSZ; \
        _Pragma("unroll") \
        for (int i = 0; i < 2; i++) { \
            int idx = tid + i*256; \
            int r = idx >> 2, cg = (idx & 3) * 8; \
            uint32_t so = (uint32_t)((r*SPAD + cg) * 2); \
            cp16(ab  + so, A  + (size_t)(m0 + r)*HDIM + (k0) + cg); \
            cp16(bb1 + so, B1 + (size_t)(n0 + r)*HDIM + (k0) + cg); \
            cp16(bb2 + so, B2 + (size_t)(n0 + r)*HDIM + (k0) + cg); \
        } \
        CP_COMMIT(); } while (0)

    LaneAddr la = lane_addr(lane, wm, wn);

    STAGE6(0, 0);
    for (int kc = 0; kc < 8; kc++) {
        if (kc < 7) STAGE6((kc+1)*32, (kc+1) & 1);
        if (kc < 7) CP_WAIT1(); else CP_WAIT0();
        __syncthreads();
        uint32_t ab = sb + (kc & 1)*3*BUFSZ;
        #pragma unroll
        for (int ks = 0; ks < 2; ks++) {
            uint32_t ah[4][4];
            #pragma unroll
            for (int mf = 0; mf < 4; mf++) {
                uint32_t aoff = (uint32_t)((la.a_off + mf*16*SPAD + ks*16) * 2);
                ldm4(ah[mf], ab + aoff);
            }
            #pragma unroll
            for (int mat = 0; mat < 2; mat++) {
                uint32_t aB = ab + (1 + mat)*BUFSZ;
                uint32_t bh[2][4];
                #pragma unroll
                for (int nf2 = 0; nf2 < 2; nf2++) {
                    uint32_t boff = (uint32_t)((la.b_off + nf2*16*SPAD + ks*16) * 2);
                    ldm4(bh[nf2], aB + boff);
                }
                #pragma unroll
                for (int mf = 0; mf < 4; mf++)
                    #pragma unroll
                    for (int nf = 0; nf < 4; nf++)
                        mma_f16(mat ? acc2[mf][nf] : acc1[mf][nf],
                                ah[mf], &bh[nf >> 1][(nf & 1)*2]);
            }
        }
        __syncthreads();
    }
    #undef STAGE6

    int tr = lane >> 2, tc = (lane & 3) * 2;
    #pragma unroll
    for (int mf = 0; mf < 4; mf++) {
        #pragma unroll
        for (int nf = 0; nf < 4; nf++) {
            int col = n0 + wn + nf*8 + tc;
            #pragma unroll
            for (int hrow = 0; hrow < 2; hrow++) {
                int m = m0 + wm + mf*16 + tr + hrow*8;
                size_t xi = (size_t)m*HDIM + col;
                float u0 = acc1[mf][nf][hrow*2+0] + b1[col];
                float u1 = acc1[mf][nf][hrow*2+1] + b1[col+1];
                float w0 = acc2[mf][nf][hrow*2+0] + b2[col];
                float w1 = acc2[mf][nf][hrow*2+1] + b2[col+1];
                float2 xv = *(float2*)(X + xi);
                xv.x += u0 / (1.f + expf(-w0));
                xv.y += u1 / (1.f + expf(-w1));
                *(float2*)(X + xi) = xv;
                if (emit_round) {
                    Xr[xi]   = __float2half_rn(xv.x);
                    Xr[xi+1] = __float2half_rn(xv.y);
                }
            }
        }
    }
}

// ---------------- host launch ----------------
extern "C" void kernel_launch(void* const* d_in, const int* in_sizes, int n_in,
                              void* d_out, int out_size)
{
    const float* latent     = (const float*)d_in[0];
    const float* W_expand   = (const float*)d_in[1];
    const float* b_expand   = (const float*)d_in[2];
    const float* norm_scale = (const float*)d_in[3];
    const float* norm_bias  = (const float*)d_in[4];
    const float* Lambda_re  = (const float*)d_in[5];
    const float* Lambda_im  = (const float*)d_in[6];
    const float* B_re       = (const float*)d_in[7];
    const float* B_im       = (const float*)d_in[8];
    const float* C_re       = (const float*)d_in[9];
    const float* C_im       = (const float*)d_in[10];
    const float* Dmat       = (const float*)d_in[11];
    const float* log_step   = (const float*)d_in[12];
    const float* W1         = (const float*)d_in[13];
    const float* b1         = (const float*)d_in[14];
    const float* W2         = (const float*)d_in[15];
    const float* b2         = (const float*)d_in[16];
    const float* W_out      = (const float*)d_in[17];
    const float* b_out      = (const float*)d_in[18];
    float* out = (float*)d_out;

    cudaFuncSetAttribute(mma_gemm,     cudaFuncAttributeMaxDynamicSharedMemorySize, SMEM_G4);
    cudaFuncSetAttribute(mma_gemm_glu, cudaFuncAttributeMaxDynamicSharedMemorySize, SMEM_G6);
    cudaFuncSetAttribute(gemm_d_ln,    cudaFuncAttributeMaxDynamicSharedMemorySize, SMEM_DLN);
    cudaFuncSetAttribute(gemm_bu_scan, cudaFuncAttributeMaxDynamicSharedMemorySize, SMEM_BUS);

    float *p_x, *p_bu;
    __half *p_h, *p_xs, *p_xh;
    __half *p_Wbt, *p_Wct, *p_W1t, *p_W2t, *p_Wot;
    cudaGetSymbolAddress((void**)&p_x,   g_x);
    cudaGetSymbolAddress((void**)&p_bu,  g_bu);
    cudaGetSymbolAddress((void**)&p_h,   g_h);
    cudaGetSymbolAddress((void**)&p_xs,  g_xs);
    cudaGetSymbolAddress((void**)&p_xh,  g_xh);
    cudaGetSymbolAddress((void**)&p_Wbt, g_Wbt);
    cudaGetSymbolAddress((void**)&p_Wct, g_Wct);
    cudaGetSymbolAddress((void**)&p_W1t, g_W1t);
    cudaGetSymbolAddress((void**)&p_W2t, g_W2t);
    cudaGetSymbolAddress((void**)&p_Wot, g_Wot);

    // setup
    expand_kernel<<<1, HDIM>>>(latent, W_expand, b_expand);
    broadcast_kernel<<<1024, 256>>>();
    setup_params<<<NLAYERS, PDIM>>>(Lambda_re, Lambda_im, B_re, B_im, C_re, C_im, log_step);
    convert_all<<<2176, 256>>>(W1, W2, W_out);

    dim3 gblk(256);
    dim3 ggrid(2, L_SEQ/128);    // (N tiles, M tiles) for 128x128 kernels
    dim3 dgrid(L_SEQ/128);       // full-row kernels (one CTA per chunk)

    for (int i = 0; i < NLAYERS; i++) {
        const float* sc = norm_scale + i*HDIM;
        const float* bi = norm_bias  + i*HDIM;
        size_t wo = (size_t)i*HDIM*HDIM;
        // 1. pre-norm: h = LN(x) -> fp16
        ln_act_kernel<<<L_SEQ/8, 256>>>(p_x, p_h, sc, bi);
        // 2. Bu' = h @ Wb' fused with within-chunk scan (writes Bu + E)
        gemm_bu_scan<<<dgrid, gblk, SMEM_BUS>>>(p_h, p_Wbt + wo, p_bu, i);
        // 3. cross-chunk prefix + in-chunk rescan; output descaled fp16
        scanC_kernel<<<NCHUNK, PDIM>>>(p_bu, p_xs, i);
        // 4. h = gelu(LN(xs @ Wc + h*D))  -- fused, t1 never materialized
        gemm_d_ln<<<dgrid, gblk, SMEM_DLN>>>(p_xs, p_Wct + wo, p_h, Dmat + i*HDIM,
                                             sc, bi, p_h);
        // 5. fused GLU pair + gate + residual (+ fp16 x copy on last layer)
        mma_gemm_glu<<<ggrid, gblk, SMEM_G6>>>(p_h, p_W1t + wo, p_W2t + wo,
                                               b1 + i*HDIM, b2 + i*HDIM,
                                               p_x, p_xh, i == NLAYERS-1 ? 1 : 0);
    }
    // output head: out = x @ W_out + b_out  (N=64, padded B to 128 rows)
    dim3 hgrid(1, L_SEQ/128);
    mma_gemm<<<hgrid, gblk, SMEM_G4>>>(p_xh, p_Wot, out, 64, 64, b_out);
}